// round 4
// baseline (speedup 1.0000x reference)
#include <cuda_runtime.h>
#include <cstdint>

// LIF scan: v = v + (x - v)/2 ; s = (v - 1 >= 0) ; v = v*(1-s)   [hard reset to 0]
// x, out: [B=64, T=200, N=4096] fp32. Each thread owns 4 neurons (one float4 column
// group) and walks T sequentially. Spike/reset done branchlessly via sign-bit mask.

#define T_STEPS 200
#define NC4     1024   // N/4 float4 groups per row
#define UB      8      // time-unroll / prefetch depth

__device__ __forceinline__ unsigned long long pack2f(float a, float b) {
    unsigned long long r;
    asm("mov.b64 %0, {%1, %2};" : "=l"(r) : "f"(a), "f"(b));
    return r;
}
__device__ __forceinline__ unsigned long long pack2u(unsigned a, unsigned b) {
    unsigned long long r;
    asm("mov.b64 %0, {%1, %2};" : "=l"(r) : "r"(a), "r"(b));
    return r;
}
__device__ __forceinline__ void unpack2f(unsigned long long p, float& a, float& b) {
    asm("mov.b64 {%0, %1}, %2;" : "=f"(a), "=f"(b) : "l"(p));
}

// One LIF step for a packed pair of neurons. Bit-exact vs reference:
//   t = RN(x - v)            fma.f32x2(v, -1, x)
//   v = RN(t*0.5 + v)        fma.f32x2(t, 0.5, v)   (t*0.5 exact, matches fused & unfused)
//   u = RN(v - 1)            add.f32x2(v, -1)       (sign(u)==0  <=>  spike)
//   mask = sign-replicate(u) : 0xFFFFFFFF if no spike, 0 if spike   (PRMT 0xbbbb)
//   sn = mask & 0x3f800000   : 1.0f if no spike, 0.0f if spike
//   s  = 1 - sn              (exact: operands in {0,1})
//   v  = v * sn              (v*1.0 exact; v*0.0 = +0 hard reset)
__device__ __forceinline__ void lif_pair(unsigned long long& v01,
                                         unsigned long long  x01,
                                         unsigned long long& s01) {
    const unsigned long long M1   = 0xBF800000BF800000ull; // (-1.0f, -1.0f)
    const unsigned long long H    = 0x3F0000003F000000ull; // ( 0.5f,  0.5f)
    const unsigned long long ONE2 = 0x3F8000003F800000ull; // ( 1.0f,  1.0f)

    unsigned long long t01, u01, sn01;
    asm("fma.rn.f32x2 %0, %1, %2, %3;" : "=l"(t01) : "l"(v01), "l"(M1), "l"(x01));
    asm("fma.rn.f32x2 %0, %1, %2, %0;" : "+l"(v01) : "l"(t01), "l"(H));
    asm("add.rn.f32x2 %0, %1, %2;"     : "=l"(u01) : "l"(v01), "l"(M1));

    unsigned u0, u1, m0, m1;
    asm("mov.b64 {%0, %1}, %2;" : "=r"(u0), "=r"(u1) : "l"(u01));
    asm("prmt.b32 %0, %1, %1, 0xbbbb;" : "=r"(m0) : "r"(u0));
    asm("prmt.b32 %0, %1, %1, 0xbbbb;" : "=r"(m1) : "r"(u1));
    asm("and.b32 %0, %0, 0x3f800000;" : "+r"(m0));
    asm("and.b32 %0, %0, 0x3f800000;" : "+r"(m1));
    sn01 = pack2u(m0, m1);

    asm("fma.rn.f32x2 %0, %1, %2, %3;" : "=l"(s01) : "l"(sn01), "l"(M1), "l"(ONE2));
    asm("mul.rn.f32x2 %0, %0, %1;"     : "+l"(v01) : "l"(sn01));
}

__device__ __forceinline__ float4 lif_step4(unsigned long long& v01,
                                            unsigned long long& v23,
                                            float4 xv) {
    unsigned long long x01 = pack2f(xv.x, xv.y);
    unsigned long long x23 = pack2f(xv.z, xv.w);
    unsigned long long s01, s23;
    lif_pair(v01, x01, s01);
    lif_pair(v23, x23, s23);
    float4 s;
    unpack2f(s01, s.x, s.y);
    unpack2f(s23, s.z, s.w);
    return s;
}

__global__ void __launch_bounds__(64)
AdaptiveLIF_kernel(const float4* __restrict__ x, float4* __restrict__ out) {
    int g = blockIdx.x * 64 + threadIdx.x;           // [0, 65536)
    int b = g >> 10;                                 // batch
    int c = g & (NC4 - 1);                           // float4 column group

    const float4* xp = x   + (size_t)b * (T_STEPS * NC4) + c;
    float4*       op = out + (size_t)b * (T_STEPS * NC4) + c;

    unsigned long long v01 = 0ull, v23 = 0ull;       // v_reset = 0

    float4 A[UB], B[UB];

    #pragma unroll
    for (int i = 0; i < UB; i++) A[i] = __ldcs(xp + i * NC4);

    // 25 bodies of 8 steps: 12 ping-pong iterations (24 bodies) + epilogue body.
    #pragma unroll 1
    for (int tb = 0; tb < T_STEPS - UB; tb += 2 * UB) {
        #pragma unroll
        for (int i = 0; i < UB; i++) B[i] = __ldcs(xp + (tb + UB + i) * NC4);
        #pragma unroll
        for (int i = 0; i < UB; i++)
            __stcs(op + (tb + i) * NC4, lif_step4(v01, v23, A[i]));
        #pragma unroll
        for (int i = 0; i < UB; i++) A[i] = __ldcs(xp + (tb + 2 * UB + i) * NC4);
        #pragma unroll
        for (int i = 0; i < UB; i++)
            __stcs(op + (tb + UB + i) * NC4, lif_step4(v01, v23, B[i]));
    }
    // Epilogue: t = 192..199 (already in A from the last iteration's prefetch)
    #pragma unroll
    for (int i = 0; i < UB; i++)
        __stcs(op + (T_STEPS - UB + i) * NC4, lif_step4(v01, v23, A[i]));
}

extern "C" void kernel_launch(void* const* d_in, const int* in_sizes, int n_in,
                              void* d_out, int out_size) {
    const float4* x = (const float4*)d_in[0];   // [64, 200, 4096] fp32
    // d_in[1] = threshold [1, 4096] — unused by the reference math
    float4* out = (float4*)d_out;               // [64, 200, 4096] fp32
    // 64*4096/4 = 65536 threads; 1024 CTAs x 64 threads -> 6.92 CTAs/SM (~1% imbalance)
    AdaptiveLIF_kernel<<<1024, 64>>>(x, out);
}